// round 16
// baseline (speedup 1.0000x reference)
#include <cuda_runtime.h>
#include <cuda_bf16.h>
#include <math.h>

#define LSEQ 4096
#define DMODEL 1024
#define NHEADS 16
#define NKV 4
#define DHEAD 64
#define KVROW (NKV * DHEAD)

// ---------------- device scratch (no allocs allowed) ----------------
__device__ float g_Q[LSEQ * DMODEL];
__device__ float g_K[LSEQ * KVROW];
__device__ float g_V[LSEQ * KVROW];
__device__ float g_A[LSEQ * DMODEL];
__device__ float2 g_rope[LSEQ * 32];

// ---------------- SGEMM: C[M,N] = A[M,K] * B[N,K]^T ----------------
__global__ __launch_bounds__(256) void sgemm_nt(const float* __restrict__ A,
                                                const float* __restrict__ B,
                                                float* __restrict__ C,
                                                int M, int N, int K) {
    __shared__ float As[16][128];
    __shared__ float Bs[16][128];
    int tid = threadIdx.x;
    int bm = blockIdx.y, bn = blockIdx.x;
    int lr = tid >> 1;
    int lc = (tid & 1) * 8;
    int ty = tid >> 4;
    int tx = tid & 15;

    float acc[8][8];
#pragma unroll
    for (int i = 0; i < 8; i++)
#pragma unroll
        for (int j = 0; j < 8; j++) acc[i][j] = 0.f;

    const float* Ap = A + (size_t)(bm * 128 + lr) * K + lc;
    const float* Bp = B + (size_t)(bn * 128 + lr) * K + lc;

    for (int kt = 0; kt < K; kt += 16) {
        float4 a0 = *reinterpret_cast<const float4*>(Ap + kt);
        float4 a1 = *reinterpret_cast<const float4*>(Ap + kt + 4);
        float4 b0 = *reinterpret_cast<const float4*>(Bp + kt);
        float4 b1 = *reinterpret_cast<const float4*>(Bp + kt + 4);
        As[lc + 0][lr] = a0.x; As[lc + 1][lr] = a0.y; As[lc + 2][lr] = a0.z; As[lc + 3][lr] = a0.w;
        As[lc + 4][lr] = a1.x; As[lc + 5][lr] = a1.y; As[lc + 6][lr] = a1.z; As[lc + 7][lr] = a1.w;
        Bs[lc + 0][lr] = b0.x; Bs[lc + 1][lr] = b0.y; Bs[lc + 2][lr] = b0.z; Bs[lc + 3][lr] = b0.w;
        Bs[lc + 4][lr] = b1.x; Bs[lc + 5][lr] = b1.y; Bs[lc + 6][lr] = b1.z; Bs[lc + 7][lr] = b1.w;
        __syncthreads();
#pragma unroll
        for (int k = 0; k < 16; k++) {
            float ra[8], rb[8];
            *reinterpret_cast<float4*>(&ra[0]) = *reinterpret_cast<float4*>(&As[k][ty * 8]);
            *reinterpret_cast<float4*>(&ra[4]) = *reinterpret_cast<float4*>(&As[k][ty * 8 + 4]);
            *reinterpret_cast<float4*>(&rb[0]) = *reinterpret_cast<float4*>(&Bs[k][tx * 8]);
            *reinterpret_cast<float4*>(&rb[4]) = *reinterpret_cast<float4*>(&Bs[k][tx * 8 + 4]);
#pragma unroll
            for (int i = 0; i < 8; i++)
#pragma unroll
                for (int j = 0; j < 8; j++) acc[i][j] += ra[i] * rb[j];
        }
        __syncthreads();
    }

#pragma unroll
    for (int i = 0; i < 8; i++) {
        float* Cp = C + (size_t)(bm * 128 + ty * 8 + i) * N + bn * 128 + tx * 8;
#pragma unroll
        for (int j4 = 0; j4 < 2; j4++) {
            float4 v;
            v.x = acc[i][j4 * 4 + 0]; v.y = acc[i][j4 * 4 + 1];
            v.z = acc[i][j4 * 4 + 2]; v.w = acc[i][j4 * 4 + 3];
            *reinterpret_cast<float4*>(Cp + j4 * 4) = v;
        }
    }
}

// ---------------- RoPE table: NEGATED angle (R15-decoded convention) --------------
// freq_i = 10000^(-2i/64), ang = -l * freq_i
__global__ void rope_table_kernel(float2* __restrict__ tab) {
    int idx = blockIdx.x * blockDim.x + threadIdx.x;
    if (idx >= LSEQ * 32) return;
    int l = idx >> 5;
    int i = idx & 31;
    double freq = pow(10000.0, -(2.0 * (double)i) / 64.0);
    double ang = -((double)l) * freq;
    double c, sn;
    sincos(ang, &c, &sn);
    tab[idx] = make_float2((float)c, (float)sn);
}

// ---------------- RoPE apply, interleaved ----------------
__global__ void rope_apply_kernel(float* __restrict__ X, const float2* __restrict__ tab,
                                  int nheads, int total_pairs) {
    int idx = blockIdx.x * blockDim.x + threadIdx.x;
    if (idx >= total_pairs) return;
    int per_row = nheads * 32;
    int l = idx / per_row;
    int r = idx - l * per_row;
    int head = r >> 5;
    int i = r & 31;
    int base = l * (nheads * 64) + head * 64 + 2 * i;
    float2 cs = tab[l * 32 + i];
    float e = X[base], o = X[base + 1];
    X[base]     = e * cs.x - o * cs.y;
    X[base + 1] = e * cs.y + o * cs.x;
}

// ---------------- Flash attention, fp32, online softmax, GQA, causal --------------
#define FL_BM 64
#define FL_BN 32

__global__ __launch_bounds__(64) void flash_kernel(const float* __restrict__ Q,
                                                   const float* __restrict__ K,
                                                   const float* __restrict__ V,
                                                   float* __restrict__ O) {
    __shared__ float Ks[FL_BN][64];
    __shared__ float Vs[FL_BN][64];
    __shared__ float S[FL_BM][FL_BN + 1];

    int tid = threadIdx.x;
    int qb = blockIdx.x;
    int h = blockIdx.y;
    int g = h >> 2;
    int qpos = qb * FL_BM + tid;

    float q[64], o[64];
    const float* qptr = Q + (size_t)qpos * DMODEL + h * DHEAD;
#pragma unroll
    for (int d = 0; d < 64; d++) { q[d] = qptr[d] * 0.125f; o[d] = 0.f; }
    float m = -1e30f, l = 0.f;

    int nkb = (qb * FL_BM + FL_BM - 1) / FL_BN + 1;
    for (int kb = 0; kb < nkb; kb++) {
        int k0 = kb * FL_BN;
#pragma unroll
        for (int it = 0; it < 8; it++) {
            int f = tid + it * 64;
            int j = f >> 4;
            int c = (f & 15) * 4;
            const float* kp = K + (size_t)(k0 + j) * KVROW + g * DHEAD + c;
            const float* vp = V + (size_t)(k0 + j) * KVROW + g * DHEAD + c;
            *reinterpret_cast<float4*>(&Ks[j][c]) = *reinterpret_cast<const float4*>(kp);
            *reinterpret_cast<float4*>(&Vs[j][c]) = *reinterpret_cast<const float4*>(vp);
        }
        __syncthreads();

        float mb = -1e30f;
#pragma unroll 4
        for (int j = 0; j < FL_BN; j++) {
            float s;
            if (k0 + j > qpos) {
                s = -1e30f;
            } else {
                s = 0.f;
                const float4* kr = reinterpret_cast<const float4*>(Ks[j]);
#pragma unroll
                for (int d4 = 0; d4 < 16; d4++) {
                    float4 kvv = kr[d4];
                    s += q[4 * d4 + 0] * kvv.x + q[4 * d4 + 1] * kvv.y
                       + q[4 * d4 + 2] * kvv.z + q[4 * d4 + 3] * kvv.w;
                }
            }
            S[tid][j] = s;
            mb = fmaxf(mb, s);
        }
        float mn = fmaxf(m, mb);
        float fac = __expf(m - mn);
        l *= fac;
#pragma unroll
        for (int d = 0; d < 64; d++) o[d] *= fac;

#pragma unroll 2
        for (int j = 0; j < FL_BN; j++) {
            float p = __expf(S[tid][j] - mn);
            l += p;
            const float4* vr = reinterpret_cast<const float4*>(Vs[j]);
#pragma unroll
            for (int d4 = 0; d4 < 16; d4++) {
                float4 vv = vr[d4];
                o[4 * d4 + 0] += p * vv.x;
                o[4 * d4 + 1] += p * vv.y;
                o[4 * d4 + 2] += p * vv.z;
                o[4 * d4 + 3] += p * vv.w;
            }
        }
        m = mn;
        __syncthreads();
    }

    float inv = 1.f / l;
    float* optr = O + (size_t)qpos * DMODEL + h * DHEAD;
#pragma unroll
    for (int d = 0; d < 64; d++) optr[d] = o[d] * inv;
}

// ---------------- launch ----------------
extern "C" void kernel_launch(void* const* d_in, const int* in_sizes, int n_in,
                              void* d_out, int out_size) {
    const float* x  = (const float*)d_in[0];
    const float* Wq = (const float*)d_in[1];
    const float* Wk = (const float*)d_in[2];
    const float* Wv = (const float*)d_in[3];
    const float* Wo = (const float*)d_in[4];
    float* out = (float*)d_out;

    float* Qd; cudaGetSymbolAddress((void**)&Qd, g_Q);
    float* Kd; cudaGetSymbolAddress((void**)&Kd, g_K);
    float* Vd; cudaGetSymbolAddress((void**)&Vd, g_V);
    float* Ad; cudaGetSymbolAddress((void**)&Ad, g_A);
    float2* Td; cudaGetSymbolAddress((void**)&Td, g_rope);

    rope_table_kernel<<<(LSEQ * 32 + 255) / 256, 256>>>(Td);

    sgemm_nt<<<dim3(DMODEL / 128, LSEQ / 128), 256>>>(x, Wq, Qd, LSEQ, DMODEL, DMODEL);
    sgemm_nt<<<dim3(KVROW / 128, LSEQ / 128), 256>>>(x, Wk, Kd, LSEQ, KVROW, DMODEL);
    sgemm_nt<<<dim3(KVROW / 128, LSEQ / 128), 256>>>(x, Wv, Vd, LSEQ, KVROW, DMODEL);

    int totQ = LSEQ * NHEADS * 32;
    rope_apply_kernel<<<(totQ + 255) / 256, 256>>>(Qd, Td, NHEADS, totQ);
    int totK = LSEQ * NKV * 32;
    rope_apply_kernel<<<(totK + 255) / 256, 256>>>(Kd, Td, NKV, totK);

    flash_kernel<<<dim3(LSEQ / FL_BM, NHEADS), FL_BM>>>(Qd, Kd, Vd, Ad);

    sgemm_nt<<<dim3(DMODEL / 128, LSEQ / 128), 256>>>(Ad, Wo, out, LSEQ, DMODEL, DMODEL);
}